// round 16
// baseline (speedup 1.0000x reference)
#include <cuda_runtime.h>
#include <math.h>

#define THREADS 256
#define INV_H 7.3f              // 511/70: reference xi = linspace(0,70,512)

// FINAL KERNEL — floor confirmed 5x (R8: 21.57us, R11: 21.76, R14: 21.63,
// R15: 21.54; harness 24.54-24.58us, rel_err 7.8e-7).
//
// One warp per row. All 32 lanes redundantly run the (warp-uniform) Newton
// solve for t = lambda*h on the index-space tilted distribution {0..511},
// then stream the 512-float row as 4 independent coalesced STG.128 per lane.
//
// Roofline status (R1..R15): 134 MB fp32 output at ~6.2 TB/s into L2 = the
// measured path-independent LTS write cap on sm_100a. Verified invariant to
// store width (.128/.256), cache ops (.cs), block size (128/256/512), fusion
// structure, and instruction density (issue 30%..75%). All other pipes have
// headroom; output bytes are fixed by the problem. This is the chip ceiling.
__global__ void __launch_bounds__(THREADS)
fused_kernel(const float* __restrict__ vel, float* __restrict__ out, int n) {
    int warp = (blockIdx.x * THREADS + threadIdx.x) >> 5;
    int lane = threadIdx.x & 31;
    if (warp >= n) return;

    float target = __ldg(&vel[warp]) * INV_H;          // mean index, [36.5, 474.5]

    // init: Cohen inverse-Langevin on y = c(256 t), ~5% accurate
    float y = (target - 255.5f) * (1.0f / 256.0f);
    y = fminf(0.92f, fmaxf(-0.92f, y));
    float t = y * __fdividef(3.0f - y * y, 1.0f - y * y) * (1.0f / 256.0f);

    // 2 slim Newton iters: large leg only (c(t/2) shifts mu by <0.0023,
    // corrected by the final full iteration). t warp-uniform -> no divergence.
    #pragma unroll
    for (int it = 0; it < 2; ++it) {
        float x = 256.0f * t;                          // |x| <= ~15.4
        float c, cp;
        if (fabsf(x) < 0.5f) {
            float x2 = x * x;
            c = x * (0.33333334f + x2 * (-0.022222223f + x2 * 0.0021164021f));
            cp = 0.33333334f + x2 * (-0.06666667f + x2 * 0.010582011f);
        } else {
            float e = __expf(2.0f * x);                // finite: |2x| <= 30.8
            float ix = __fdividef(1.0f, x);
            c = 1.0f + __fdividef(2.0f, e - 1.0f) - ix;    // coth(x) - 1/x
            cp = 1.0f - 2.0f * c * ix - c * c;
        }
        t -= __fdividef(255.5f + 256.0f * c - target, 65536.0f * cp);
        t = fminf(0.06f, fmaxf(-0.06f, t));
    }

    // final full-model iteration (adds the small leg c(t/2))
    {
        float u = 0.5f * t;
        float u2 = u * u;
        float c1 = u * (0.33333334f - u2 * 0.022222223f);
        float cp1 = 0.33333334f - u2 * 0.06666667f;
        float x = 256.0f * t;
        float c, cp;
        if (fabsf(x) < 0.5f) {
            float x2 = x * x;
            c = x * (0.33333334f + x2 * (-0.022222223f + x2 * 0.0021164021f));
            cp = 0.33333334f + x2 * (-0.06666667f + x2 * 0.010582011f);
        } else {
            float e = __expf(2.0f * x);
            float ix = __fdividef(1.0f, x);
            c = 1.0f + __fdividef(2.0f, e - 1.0f) - ix;
            cp = 1.0f - 2.0f * c * ix - c * c;
        }
        float mu = 255.5f + 256.0f * c - 0.5f * c1;
        float var = 65536.0f * cp - 0.25f * cp1;
        t -= __fdividef(mu - target, var);
        t = fminf(0.06f, fmaxf(-0.06f, t));
    }

    // mu0 = -logS0 = -(log512 + 255.5 t + log_sinhc(256t) - log_sinhc(t/2))
    float u = 0.5f * t;
    float ls;                                          // log_sinhc(256t)
    {
        float ax = fabsf(256.0f * t);
        if (ax < 0.5f) {
            float x2 = ax * ax;
            ls = x2 * (0.16666667f - x2 * 0.0055555556f);
        } else {
            float s = 0.5f * (__expf(ax) - __expf(-ax));
            ls = __logf(__fdividef(s, ax));
        }
    }
    float mu0 = -(6.2383246f + 255.5f * t + ls - u * u * 0.16666667f);

    // f[j] = exp(mu0 + t*j): lane l anchors j=4l; in-vector ladder r,r^2,r^3;
    // 4 INDEPENDENT chunk bases v0..v3 (no serial chain between stores).
    float r  = __expf(t);
    float R  = __expf(128.0f * t);
    float r2 = r * r;
    float r3 = r2 * r;
    float R2 = R * R;
    float v0 = __expf(fmaf(t, (float)(lane << 2), mu0));
    float v1 = v0 * R;
    float v2 = v0 * R2;
    float v3 = v1 * R2;
    float4* o = reinterpret_cast<float4*>(out) + (size_t)warp * 128 + lane;
    o[0]  = make_float4(v0, v0 * r, v0 * r2, v0 * r3);
    o[32] = make_float4(v1, v1 * r, v1 * r2, v1 * r3);
    o[64] = make_float4(v2, v2 * r, v2 * r2, v2 * r3);
    o[96] = make_float4(v3, v3 * r, v3 * r2, v3 * r3);
}

extern "C" void kernel_launch(void* const* d_in, const int* in_sizes, int n_in,
                              void* d_out, int out_size) {
    const float* vel = (const float*)d_in[0];
    int n = in_sizes[0];
    if (n_in >= 2 && in_sizes[0] < in_sizes[1]) {   // defensive: vel is the large buffer
        vel = (const float*)d_in[1];
        n = in_sizes[1];
    }
    float* out = (float*)d_out;
    int warps_per_block = THREADS / 32;
    int blocks = (n + warps_per_block - 1) / warps_per_block;   // 8192 for n=65536
    fused_kernel<<<blocks, THREADS>>>(vel, out, n);
}

// round 17
// speedup vs baseline: 1.0158x; 1.0158x over previous
#include <cuda_runtime.h>
#include <math.h>

#define THREADS 256
#define INV_H 7.3f              // 511/70: reference xi = linspace(0,70,512)

// FINAL KERNEL — floor confirmed 6x across R8/R11/R12/R14/R15/R16
// (21.54-21.98us kernel, 24.54-24.67us harness, rel_err 7.80888e-07).
//
// One warp per row. All 32 lanes redundantly run the (warp-uniform) Newton
// solve for t = lambda*h on the index-space tilted distribution {0..511},
// then stream the 512-float row as 4 independent coalesced STG.128 per lane.
//
// Roofline status (R1..R16): 134 MB fp32 output at ~6.2 TB/s into L2 = the
// measured path-independent LTS write cap on sm_100a. Verified invariant to
// store width (.128/.256), cache ops (.cs), block size (128/256/512), fusion
// structure, and instruction density (issue 30%..75%). All other pipes have
// headroom; output bytes are fixed by the problem. This is the chip ceiling.
__global__ void __launch_bounds__(THREADS)
fused_kernel(const float* __restrict__ vel, float* __restrict__ out, int n) {
    int warp = (blockIdx.x * THREADS + threadIdx.x) >> 5;
    int lane = threadIdx.x & 31;
    if (warp >= n) return;

    float target = __ldg(&vel[warp]) * INV_H;          // mean index, [36.5, 474.5]

    // init: Cohen inverse-Langevin on y = c(256 t), ~5% accurate
    float y = (target - 255.5f) * (1.0f / 256.0f);
    y = fminf(0.92f, fmaxf(-0.92f, y));
    float t = y * __fdividef(3.0f - y * y, 1.0f - y * y) * (1.0f / 256.0f);

    // 2 slim Newton iters: large leg only (c(t/2) shifts mu by <0.0023,
    // corrected by the final full iteration). t warp-uniform -> no divergence.
    #pragma unroll
    for (int it = 0; it < 2; ++it) {
        float x = 256.0f * t;                          // |x| <= ~15.4
        float c, cp;
        if (fabsf(x) < 0.5f) {
            float x2 = x * x;
            c = x * (0.33333334f + x2 * (-0.022222223f + x2 * 0.0021164021f));
            cp = 0.33333334f + x2 * (-0.06666667f + x2 * 0.010582011f);
        } else {
            float e = __expf(2.0f * x);                // finite: |2x| <= 30.8
            float ix = __fdividef(1.0f, x);
            c = 1.0f + __fdividef(2.0f, e - 1.0f) - ix;    // coth(x) - 1/x
            cp = 1.0f - 2.0f * c * ix - c * c;
        }
        t -= __fdividef(255.5f + 256.0f * c - target, 65536.0f * cp);
        t = fminf(0.06f, fmaxf(-0.06f, t));
    }

    // final full-model iteration (adds the small leg c(t/2))
    {
        float u = 0.5f * t;
        float u2 = u * u;
        float c1 = u * (0.33333334f - u2 * 0.022222223f);
        float cp1 = 0.33333334f - u2 * 0.06666667f;
        float x = 256.0f * t;
        float c, cp;
        if (fabsf(x) < 0.5f) {
            float x2 = x * x;
            c = x * (0.33333334f + x2 * (-0.022222223f + x2 * 0.0021164021f));
            cp = 0.33333334f + x2 * (-0.06666667f + x2 * 0.010582011f);
        } else {
            float e = __expf(2.0f * x);
            float ix = __fdividef(1.0f, x);
            c = 1.0f + __fdividef(2.0f, e - 1.0f) - ix;
            cp = 1.0f - 2.0f * c * ix - c * c;
        }
        float mu = 255.5f + 256.0f * c - 0.5f * c1;
        float var = 65536.0f * cp - 0.25f * cp1;
        t -= __fdividef(mu - target, var);
        t = fminf(0.06f, fmaxf(-0.06f, t));
    }

    // mu0 = -logS0 = -(log512 + 255.5 t + log_sinhc(256t) - log_sinhc(t/2))
    float u = 0.5f * t;
    float ls;                                          // log_sinhc(256t)
    {
        float ax = fabsf(256.0f * t);
        if (ax < 0.5f) {
            float x2 = ax * ax;
            ls = x2 * (0.16666667f - x2 * 0.0055555556f);
        } else {
            float s = 0.5f * (__expf(ax) - __expf(-ax));
            ls = __logf(__fdividef(s, ax));
        }
    }
    float mu0 = -(6.2383246f + 255.5f * t + ls - u * u * 0.16666667f);

    // f[j] = exp(mu0 + t*j): lane l anchors j=4l; in-vector ladder r,r^2,r^3;
    // 4 INDEPENDENT chunk bases v0..v3 (no serial chain between stores).
    float r  = __expf(t);
    float R  = __expf(128.0f * t);
    float r2 = r * r;
    float r3 = r2 * r;
    float R2 = R * R;
    float v0 = __expf(fmaf(t, (float)(lane << 2), mu0));
    float v1 = v0 * R;
    float v2 = v0 * R2;
    float v3 = v1 * R2;
    float4* o = reinterpret_cast<float4*>(out) + (size_t)warp * 128 + lane;
    o[0]  = make_float4(v0, v0 * r, v0 * r2, v0 * r3);
    o[32] = make_float4(v1, v1 * r, v1 * r2, v1 * r3);
    o[64] = make_float4(v2, v2 * r, v2 * r2, v2 * r3);
    o[96] = make_float4(v3, v3 * r, v3 * r2, v3 * r3);
}

extern "C" void kernel_launch(void* const* d_in, const int* in_sizes, int n_in,
                              void* d_out, int out_size) {
    const float* vel = (const float*)d_in[0];
    int n = in_sizes[0];
    if (n_in >= 2 && in_sizes[0] < in_sizes[1]) {   // defensive: vel is the large buffer
        vel = (const float*)d_in[1];
        n = in_sizes[1];
    }
    float* out = (float*)d_out;
    int warps_per_block = THREADS / 32;
    int blocks = (n + warps_per_block - 1) / warps_per_block;   // 8192 for n=65536
    fused_kernel<<<blocks, THREADS>>>(vel, out, n);
}